// round 1
// baseline (speedup 1.0000x reference)
#include <cuda_runtime.h>
#include <math.h>

#define BB 4
#define TT 16
#define HH 64
#define WW 64
#define CIN 32
#define COUT 64
#define GG (4*COUT)   // 256 gate channels

// Scratch: gx for all (b,t) pixels: (B*T*H*W, 256) floats = 268MB
__device__ float g_gx[(size_t)BB*TT*HH*WW*GG];
// Ping-pong hidden state + cell state: (B*H*W, 64)
__device__ float g_h0[BB*HH*WW*COUT];
__device__ float g_h1[BB*HH*WW*COUT];
__device__ float g_c [BB*HH*WW*COUT];

// ---------------------------------------------------------------------------
// Phase 1: input-to-gate conv for all B*T images at once.
// gx[bt,y,x,:] = bias + sum_{ky,kx,ci} x[bt,y+ky-1,x+kx-1,ci] * w[ky,kx,ci,:]
// Thread: one pixel x 16 output channels (4 float4 accumulators).
// Block: 256 threads = 16 pixels x 16 oc-groups.
// ---------------------------------------------------------------------------
__global__ __launch_bounds__(256)
void input_conv_kernel(const float* __restrict__ x,
                       const float* __restrict__ wk,
                       const float* __restrict__ bias)
{
    const int tx  = threadIdx.x;
    const int oc0 = (tx & 15) * 16;                 // 0,16,...,240
    const int pix = blockIdx.x * 16 + (tx >> 4);    // 0 .. B*T*H*W-1
    const int bt  = pix >> 12;                      // /4096
    const int rem = pix & 4095;
    const int py  = rem >> 6;
    const int px  = rem & 63;

    float4 a0 = *(const float4*)(bias + oc0 + 0);
    float4 a1 = *(const float4*)(bias + oc0 + 4);
    float4 a2 = *(const float4*)(bias + oc0 + 8);
    float4 a3 = *(const float4*)(bias + oc0 + 12);

    #pragma unroll
    for (int ky = 0; ky < 3; ky++) {
        const int iy = py + ky - 1;
        if ((unsigned)iy >= HH) continue;
        #pragma unroll
        for (int kx = 0; kx < 3; kx++) {
            const int ix = px + kx - 1;
            if ((unsigned)ix >= WW) continue;
            const float* __restrict__ xp = x + ((size_t)(bt*HH + iy)*WW + ix)*CIN;
            const float* __restrict__ wp = wk + (size_t)((ky*3+kx)*CIN)*GG + oc0;
            #pragma unroll 4
            for (int ci = 0; ci < CIN; ci++) {
                const float xv = xp[ci];
                const float* __restrict__ wr = wp + (size_t)ci*GG;
                float4 w0 = *(const float4*)(wr + 0);
                float4 w1 = *(const float4*)(wr + 4);
                float4 w2 = *(const float4*)(wr + 8);
                float4 w3 = *(const float4*)(wr + 12);
                a0.x = fmaf(xv, w0.x, a0.x); a0.y = fmaf(xv, w0.y, a0.y);
                a0.z = fmaf(xv, w0.z, a0.z); a0.w = fmaf(xv, w0.w, a0.w);
                a1.x = fmaf(xv, w1.x, a1.x); a1.y = fmaf(xv, w1.y, a1.y);
                a1.z = fmaf(xv, w1.z, a1.z); a1.w = fmaf(xv, w1.w, a1.w);
                a2.x = fmaf(xv, w2.x, a2.x); a2.y = fmaf(xv, w2.y, a2.y);
                a2.z = fmaf(xv, w2.z, a2.z); a2.w = fmaf(xv, w2.w, a2.w);
                a3.x = fmaf(xv, w3.x, a3.x); a3.y = fmaf(xv, w3.y, a3.y);
                a3.z = fmaf(xv, w3.z, a3.z); a3.w = fmaf(xv, w3.w, a3.w);
            }
        }
    }

    float* __restrict__ o = g_gx + (size_t)pix*GG + oc0;
    *(float4*)(o + 0)  = a0;
    *(float4*)(o + 4)  = a1;
    *(float4*)(o + 8)  = a2;
    *(float4*)(o + 12) = a3;
}

__device__ __forceinline__ float hsig(float z) {
    return fminf(fmaxf(0.2f*z + 0.5f, 0.0f), 1.0f);
}

// ---------------------------------------------------------------------------
// Phase 2: one recurrent step.
// g = gx[:,t] + conv(h_prev, rec_kernel); gates i,f,c,o; update c,h; write
// y[:,t] = h * inv + add  (BN inference affine).
// Thread: one pixel x 4 channels x all 4 gates (16 accumulators) so the gate
// combination is fully in-register. Buffers picked from t&1 inside the kernel.
// ---------------------------------------------------------------------------
template<bool FIRST>
__global__ __launch_bounds__(256)
void step_kernel(const float* __restrict__ rw,
                 float* __restrict__ y,
                 const int t,
                 const float* __restrict__ gamma,
                 const float* __restrict__ beta,
                 const float* __restrict__ mmean,
                 const float* __restrict__ mvar)
{
    const float* __restrict__ hprev = (t & 1) ? g_h0 : g_h1;
    float*       __restrict__ hnew  = (t & 1) ? g_h1 : g_h0;

    const int tx  = threadIdx.x;
    const int co0 = (tx & 15) * 4;                  // 0,4,...,60
    const int pix = blockIdx.x * 16 + (tx >> 4);    // 0 .. B*H*W-1
    const int b   = pix >> 12;
    const int rem = pix & 4095;
    const int py  = rem >> 6;
    const int px  = rem & 63;

    const float* __restrict__ gp = g_gx + ((size_t)(b*TT + t)*HH*WW + rem)*GG;
    float4 ai = *(const float4*)(gp + 0*COUT + co0);
    float4 af = *(const float4*)(gp + 1*COUT + co0);
    float4 ag = *(const float4*)(gp + 2*COUT + co0);
    float4 ao = *(const float4*)(gp + 3*COUT + co0);

    if (!FIRST) {
        #pragma unroll
        for (int ky = 0; ky < 3; ky++) {
            const int iy = py + ky - 1;
            if ((unsigned)iy >= HH) continue;
            #pragma unroll
            for (int kx = 0; kx < 3; kx++) {
                const int ix = px + kx - 1;
                if ((unsigned)ix >= WW) continue;
                const float* __restrict__ hp = hprev + (size_t)((b*HH + iy)*WW + ix)*COUT;
                const float* __restrict__ wp = rw + (size_t)((ky*3+kx)*COUT)*GG;
                #pragma unroll 4
                for (int ci = 0; ci < COUT; ci++) {
                    const float hv = hp[ci];
                    const float* __restrict__ wr = wp + (size_t)ci*GG;
                    float4 wi = *(const float4*)(wr + 0*COUT + co0);
                    float4 wf = *(const float4*)(wr + 1*COUT + co0);
                    float4 wg = *(const float4*)(wr + 2*COUT + co0);
                    float4 wo = *(const float4*)(wr + 3*COUT + co0);
                    ai.x = fmaf(hv, wi.x, ai.x); ai.y = fmaf(hv, wi.y, ai.y);
                    ai.z = fmaf(hv, wi.z, ai.z); ai.w = fmaf(hv, wi.w, ai.w);
                    af.x = fmaf(hv, wf.x, af.x); af.y = fmaf(hv, wf.y, af.y);
                    af.z = fmaf(hv, wf.z, af.z); af.w = fmaf(hv, wf.w, af.w);
                    ag.x = fmaf(hv, wg.x, ag.x); ag.y = fmaf(hv, wg.y, ag.y);
                    ag.z = fmaf(hv, wg.z, ag.z); ag.w = fmaf(hv, wg.w, ag.w);
                    ao.x = fmaf(hv, wo.x, ao.x); ao.y = fmaf(hv, wo.y, ao.y);
                    ao.z = fmaf(hv, wo.z, ao.z); ao.w = fmaf(hv, wo.w, ao.w);
                }
            }
        }
    }

    // Gates (Keras hard_sigmoid for i,f,o; tanh for candidate)
    float4 i4, f4, o4;
    i4.x = hsig(ai.x); i4.y = hsig(ai.y); i4.z = hsig(ai.z); i4.w = hsig(ai.w);
    f4.x = hsig(af.x); f4.y = hsig(af.y); f4.z = hsig(af.z); f4.w = hsig(af.w);
    o4.x = hsig(ao.x); o4.y = hsig(ao.y); o4.z = hsig(ao.z); o4.w = hsig(ao.w);

    float* __restrict__ cp = g_c + (size_t)pix*COUT + co0;
    float4 cold = FIRST ? make_float4(0.f,0.f,0.f,0.f) : *(const float4*)cp;

    float4 cn;
    cn.x = f4.x*cold.x + i4.x*tanhf(ag.x);
    cn.y = f4.y*cold.y + i4.y*tanhf(ag.y);
    cn.z = f4.z*cold.z + i4.z*tanhf(ag.z);
    cn.w = f4.w*cold.w + i4.w*tanhf(ag.w);
    *(float4*)cp = cn;

    float4 h4;
    h4.x = o4.x * tanhf(cn.x);
    h4.y = o4.y * tanhf(cn.y);
    h4.z = o4.z * tanhf(cn.z);
    h4.w = o4.w * tanhf(cn.w);
    *(float4*)(hnew + (size_t)pix*COUT + co0) = h4;

    // BatchNorm (inference): y = h*inv + (beta - mean*inv)
    float4 gm = *(const float4*)(gamma + co0);
    float4 bt4 = *(const float4*)(beta  + co0);
    float4 mm = *(const float4*)(mmean + co0);
    float4 mv = *(const float4*)(mvar  + co0);
    float4 inv, add, yv;
    inv.x = gm.x * rsqrtf(mv.x + 1e-3f); add.x = bt4.x - mm.x*inv.x;
    inv.y = gm.y * rsqrtf(mv.y + 1e-3f); add.y = bt4.y - mm.y*inv.y;
    inv.z = gm.z * rsqrtf(mv.z + 1e-3f); add.z = bt4.z - mm.z*inv.z;
    inv.w = gm.w * rsqrtf(mv.w + 1e-3f); add.w = bt4.w - mm.w*inv.w;
    yv.x = h4.x*inv.x + add.x;
    yv.y = h4.y*inv.y + add.y;
    yv.z = h4.z*inv.z + add.z;
    yv.w = h4.w*inv.w + add.w;

    // Output layout (B,T,H,W,COUT)
    float* __restrict__ yp = y + ((size_t)(b*TT + t)*HH*WW + rem)*COUT + co0;
    *(float4*)yp = yv;
}

extern "C" void kernel_launch(void* const* d_in, const int* in_sizes, int n_in,
                              void* d_out, int out_size)
{
    const float* x      = (const float*)d_in[0];
    const float* wk     = (const float*)d_in[1];
    const float* rw     = (const float*)d_in[2];
    const float* bias   = (const float*)d_in[3];
    const float* gamma  = (const float*)d_in[4];
    const float* beta   = (const float*)d_in[5];
    const float* mmean  = (const float*)d_in[6];
    const float* mvar   = (const float*)d_in[7];
    float* y = (float*)d_out;

    // Phase 1: all input convs at once. 262144 pixels / 16 per block.
    input_conv_kernel<<<(BB*TT*HH*WW)/16, 256>>>(x, wk, bias);

    // Phase 2: 16 sequential recurrent steps. 16384 pixels / 16 per block.
    const int nblk = (BB*HH*WW)/16;
    step_kernel<true><<<nblk, 256>>>(rw, y, 0, gamma, beta, mmean, mvar);
    for (int t = 1; t < TT; t++) {
        step_kernel<false><<<nblk, 256>>>(rw, y, t, gamma, beta, mmean, mvar);
    }
}

// round 2
// speedup vs baseline: 2.9801x; 2.9801x over previous
#include <cuda_runtime.h>
#include <math.h>

#define BB 4
#define TT 16
#define HH 64
#define WW 64
#define CIN 32
#define COUT 64
#define GG (4*COUT)   // 256 gate channels

// Scratch: gx for all (b,t) pixels: (B*T*H*W, 256) floats = 268MB
__device__ float g_gx[(size_t)BB*TT*HH*WW*GG];
// Ping-pong hidden state + cell state: (B*H*W, 64)
__device__ float g_h0[BB*HH*WW*COUT];
__device__ float g_h1[BB*HH*WW*COUT];
__device__ float g_c [BB*HH*WW*COUT];

__device__ __forceinline__ float hsig(float z) {
    return fminf(fmaxf(0.2f*z + 0.5f, 0.0f), 1.0f);
}

#define FMA4(A, W, S) \
    A.x = fmaf(S, W.x, A.x); A.y = fmaf(S, W.y, A.y); \
    A.z = fmaf(S, W.z, A.z); A.w = fmaf(S, W.w, A.w);

// ---------------------------------------------------------------------------
// Phase 1: input-to-gate conv. Thread: 4 pixels (along x) x 16 outputs
// (4 per "gate" slot g*64+co0). Weight loads amortized over 4 pixels.
// Block: 128 threads = 8 pixel-groups (32 px, half a row) x 16 oc-groups.
// Grid: B*T*H*2 = 8192.
// ---------------------------------------------------------------------------
__global__ __launch_bounds__(128)
void input_conv_kernel(const float* __restrict__ x,
                       const float* __restrict__ wk,
                       const float* __restrict__ bias)
{
    const int tx  = threadIdx.x;
    const int co0 = (tx & 15) * 4;
    const int pg  = tx >> 4;                 // 0..7
    const int bid = blockIdx.x;
    const int bt  = bid >> 7;                // 0..63 (B*T)
    const int r   = bid & 127;
    const int py  = r >> 1;
    const int px0 = (r & 1) * 32 + pg * 4;

    float4 acc[4][4];                        // [gate][pixel]
    #pragma unroll
    for (int g = 0; g < 4; g++) {
        float4 bv = *(const float4*)(bias + g*COUT + co0);
        #pragma unroll
        for (int p = 0; p < 4; p++) acc[g][p] = bv;
    }

    #pragma unroll
    for (int ky = 0; ky < 3; ky++) {
        const int iy = py + ky - 1;
        if ((unsigned)iy >= HH) continue;
        const float* __restrict__ xrow = x + ((size_t)(bt*HH + iy)*WW)*CIN;
        #pragma unroll 1
        for (int ci = 0; ci < CIN; ci++) {
            float hv[6];
            #pragma unroll
            for (int j = 0; j < 6; j++) {
                const int ix = px0 - 1 + j;
                hv[j] = ((unsigned)ix < WW) ? xrow[(size_t)ix*CIN + ci] : 0.0f;
            }
            #pragma unroll
            for (int kx = 0; kx < 3; kx++) {
                const float* __restrict__ wr = wk + (size_t)((ky*3+kx)*CIN + ci)*GG;
                float4 w0 = *(const float4*)(wr + 0*COUT + co0);
                float4 w1 = *(const float4*)(wr + 1*COUT + co0);
                float4 w2 = *(const float4*)(wr + 2*COUT + co0);
                float4 w3 = *(const float4*)(wr + 3*COUT + co0);
                #pragma unroll
                for (int p = 0; p < 4; p++) {
                    const float s = hv[p + kx];
                    FMA4(acc[0][p], w0, s);
                    FMA4(acc[1][p], w1, s);
                    FMA4(acc[2][p], w2, s);
                    FMA4(acc[3][p], w3, s);
                }
            }
        }
    }

    const size_t rowbase = ((size_t)bt*HH + py)*WW;
    #pragma unroll
    for (int p = 0; p < 4; p++) {
        float* __restrict__ o = g_gx + (rowbase + px0 + p)*GG + co0;
        *(float4*)(o + 0*COUT) = acc[0][p];
        *(float4*)(o + 1*COUT) = acc[1][p];
        *(float4*)(o + 2*COUT) = acc[2][p];
        *(float4*)(o + 3*COUT) = acc[3][p];
    }
}

// ---------------------------------------------------------------------------
// Phase 2: one recurrent step. Thread: 4 pixels x 4 channels x 4 gates
// (64 accumulators). Weight loads amortized over 4 pixels.
// Block: 128 threads = 8 pixel-groups (32 px) x 16 channel-groups.
// Grid: B*H*2 = 512.
// ---------------------------------------------------------------------------
template<bool FIRST>
__global__ __launch_bounds__(128)
void step_kernel(const float* __restrict__ rw,
                 float* __restrict__ y,
                 const int t,
                 const float* __restrict__ gamma,
                 const float* __restrict__ beta,
                 const float* __restrict__ mmean,
                 const float* __restrict__ mvar)
{
    const float* __restrict__ hprev = (t & 1) ? g_h0 : g_h1;
    float*       __restrict__ hnew  = (t & 1) ? g_h1 : g_h0;

    const int tx  = threadIdx.x;
    const int co0 = (tx & 15) * 4;
    const int pg  = tx >> 4;
    const int bid = blockIdx.x;
    const int b   = bid >> 7;
    const int r   = bid & 127;
    const int py  = r >> 1;
    const int px0 = (r & 1) * 32 + pg * 4;

    float4 acc[4][4];                        // [gate][pixel]
    const size_t gxrow = ((size_t)(b*TT + t)*HH + py)*WW;
    #pragma unroll
    for (int p = 0; p < 4; p++) {
        const float* __restrict__ gp = g_gx + (gxrow + px0 + p)*GG + co0;
        acc[0][p] = *(const float4*)(gp + 0*COUT);
        acc[1][p] = *(const float4*)(gp + 1*COUT);
        acc[2][p] = *(const float4*)(gp + 2*COUT);
        acc[3][p] = *(const float4*)(gp + 3*COUT);
    }

    if (!FIRST) {
        #pragma unroll
        for (int ky = 0; ky < 3; ky++) {
            const int iy = py + ky - 1;
            if ((unsigned)iy >= HH) continue;
            const float* __restrict__ hrow = hprev + ((size_t)(b*HH + iy)*WW)*COUT;
            #pragma unroll 1
            for (int ci = 0; ci < COUT; ci++) {
                float hv[6];
                #pragma unroll
                for (int j = 0; j < 6; j++) {
                    const int ix = px0 - 1 + j;
                    hv[j] = ((unsigned)ix < WW) ? hrow[(size_t)ix*COUT + ci] : 0.0f;
                }
                #pragma unroll
                for (int kx = 0; kx < 3; kx++) {
                    const float* __restrict__ wr = rw + (size_t)((ky*3+kx)*COUT + ci)*GG;
                    float4 w0 = *(const float4*)(wr + 0*COUT + co0);
                    float4 w1 = *(const float4*)(wr + 1*COUT + co0);
                    float4 w2 = *(const float4*)(wr + 2*COUT + co0);
                    float4 w3 = *(const float4*)(wr + 3*COUT + co0);
                    #pragma unroll
                    for (int p = 0; p < 4; p++) {
                        const float s = hv[p + kx];
                        FMA4(acc[0][p], w0, s);
                        FMA4(acc[1][p], w1, s);
                        FMA4(acc[2][p], w2, s);
                        FMA4(acc[3][p], w3, s);
                    }
                }
            }
        }
    }

    // BN constants for this thread's 4 channels
    float4 gm  = *(const float4*)(gamma + co0);
    float4 bt4 = *(const float4*)(beta  + co0);
    float4 mm  = *(const float4*)(mmean + co0);
    float4 mv  = *(const float4*)(mvar  + co0);
    float4 inv, add;
    inv.x = gm.x * rsqrtf(mv.x + 1e-3f); add.x = bt4.x - mm.x*inv.x;
    inv.y = gm.y * rsqrtf(mv.y + 1e-3f); add.y = bt4.y - mm.y*inv.y;
    inv.z = gm.z * rsqrtf(mv.z + 1e-3f); add.z = bt4.z - mm.z*inv.z;
    inv.w = gm.w * rsqrtf(mv.w + 1e-3f); add.w = bt4.w - mm.w*inv.w;

    const size_t pixrow = ((size_t)b*HH + py)*WW;
    #pragma unroll
    for (int p = 0; p < 4; p++) {
        const size_t pix = pixrow + px0 + p;

        float4 i4, f4, o4;
        i4.x = hsig(acc[0][p].x); i4.y = hsig(acc[0][p].y);
        i4.z = hsig(acc[0][p].z); i4.w = hsig(acc[0][p].w);
        f4.x = hsig(acc[1][p].x); f4.y = hsig(acc[1][p].y);
        f4.z = hsig(acc[1][p].z); f4.w = hsig(acc[1][p].w);
        o4.x = hsig(acc[3][p].x); o4.y = hsig(acc[3][p].y);
        o4.z = hsig(acc[3][p].z); o4.w = hsig(acc[3][p].w);

        float* __restrict__ cp = g_c + pix*COUT + co0;
        float4 cold = FIRST ? make_float4(0.f,0.f,0.f,0.f) : *(const float4*)cp;

        float4 cn;
        cn.x = f4.x*cold.x + i4.x*tanhf(acc[2][p].x);
        cn.y = f4.y*cold.y + i4.y*tanhf(acc[2][p].y);
        cn.z = f4.z*cold.z + i4.z*tanhf(acc[2][p].z);
        cn.w = f4.w*cold.w + i4.w*tanhf(acc[2][p].w);
        *(float4*)cp = cn;

        float4 h4;
        h4.x = o4.x * tanhf(cn.x);
        h4.y = o4.y * tanhf(cn.y);
        h4.z = o4.z * tanhf(cn.z);
        h4.w = o4.w * tanhf(cn.w);
        *(float4*)(hnew + pix*COUT + co0) = h4;

        float4 yv;
        yv.x = h4.x*inv.x + add.x;
        yv.y = h4.y*inv.y + add.y;
        yv.z = h4.z*inv.z + add.z;
        yv.w = h4.w*inv.w + add.w;
        float* __restrict__ yp = y + ((gxrow + px0 + p))*COUT + co0;
        *(float4*)yp = yv;
    }
}

extern "C" void kernel_launch(void* const* d_in, const int* in_sizes, int n_in,
                              void* d_out, int out_size)
{
    const float* x      = (const float*)d_in[0];
    const float* wk     = (const float*)d_in[1];
    const float* rw     = (const float*)d_in[2];
    const float* bias   = (const float*)d_in[3];
    const float* gamma  = (const float*)d_in[4];
    const float* beta   = (const float*)d_in[5];
    const float* mmean  = (const float*)d_in[6];
    const float* mvar   = (const float*)d_in[7];
    float* y = (float*)d_out;

    // Phase 1: all input convs. 8192 blocks x 128 threads (32 px each).
    input_conv_kernel<<<BB*TT*HH*2, 128>>>(x, wk, bias);

    // Phase 2: 16 sequential recurrent steps. 512 blocks x 128 threads.
    const int nblk = BB*HH*2;
    step_kernel<true><<<nblk, 128>>>(rw, y, 0, gamma, beta, mmean, mvar);
    for (int t = 1; t < TT; t++) {
        step_kernel<false><<<nblk, 128>>>(rw, y, t, gamma, beta, mmean, mvar);
    }
}

// round 3
// speedup vs baseline: 3.3856x; 1.1361x over previous
#include <cuda_runtime.h>
#include <math.h>

#define BB 4
#define TT 16
#define HH 64
#define WW 64
#define CIN 32
#define COUT 64
#define GG (4*COUT)   // 256 gate channels

// Scratch: gx for all (b,t) pixels: (B*T*H*W, 256) floats = 268MB
__device__ float g_gx[(size_t)BB*TT*HH*WW*GG];
// Ping-pong hidden state + cell state: (B*H*W, 64)
__device__ float g_h0[BB*HH*WW*COUT];
__device__ float g_h1[BB*HH*WW*COUT];
__device__ float g_c [BB*HH*WW*COUT];

__device__ __forceinline__ float hsig(float z) {
    return fminf(fmaxf(0.2f*z + 0.5f, 0.0f), 1.0f);
}

#define FMA2(A, W, S) \
    A.x = fmaf(S, W.x, A.x); A.y = fmaf(S, W.y, A.y);

// ---------------------------------------------------------------------------
// Phase 1: input-to-gate conv.
// Thread: 4 pixels x (2 channels x 4 gates) = 32 accumulators.
// Block: 128 thr = 4 pixel-groups (16 px) x 32 channel-groups.
//        Warp lanes share pixels -> hv loads are warp-uniform broadcasts.
// Grid: B*T*H*4 = 16384.
// ---------------------------------------------------------------------------
__global__ __launch_bounds__(128, 5)
void input_conv_kernel(const float* __restrict__ x,
                       const float* __restrict__ wk,
                       const float* __restrict__ bias)
{
    const int tx  = threadIdx.x;
    const int co0 = (tx & 31) * 2;           // 0,2,...,62
    const int pg  = tx >> 5;                 // 0..3  (== warp id)
    const int bid = blockIdx.x;
    const int bt  = bid >> 8;                // /256
    const int r   = bid & 255;
    const int py  = r >> 2;
    const int px0 = (r & 3) * 16 + pg * 4;

    float2 acc[4][4];                        // [gate][pixel]
    #pragma unroll
    for (int g = 0; g < 4; g++) {
        float2 bv = *(const float2*)(bias + g*COUT + co0);
        #pragma unroll
        for (int p = 0; p < 4; p++) acc[g][p] = bv;
    }

    #pragma unroll
    for (int ky = 0; ky < 3; ky++) {
        const int iy = py + ky - 1;
        if ((unsigned)iy >= HH) continue;
        const float* __restrict__ xrow = x + ((size_t)(bt*HH + iy)*WW)*CIN;
        #pragma unroll 1
        for (int ci = 0; ci < CIN; ci++) {
            float hv[6];
            #pragma unroll
            for (int j = 0; j < 6; j++) {
                const int ix = px0 - 1 + j;
                hv[j] = ((unsigned)ix < WW) ? xrow[(size_t)ix*CIN + ci] : 0.0f;
            }
            #pragma unroll
            for (int kx = 0; kx < 3; kx++) {
                const float* __restrict__ wr = wk + (size_t)((ky*3+kx)*CIN + ci)*GG + co0;
                float2 w0 = *(const float2*)(wr + 0*COUT);
                float2 w1 = *(const float2*)(wr + 1*COUT);
                float2 w2 = *(const float2*)(wr + 2*COUT);
                float2 w3 = *(const float2*)(wr + 3*COUT);
                #pragma unroll
                for (int p = 0; p < 4; p++) {
                    const float s = hv[p + kx];
                    FMA2(acc[0][p], w0, s);
                    FMA2(acc[1][p], w1, s);
                    FMA2(acc[2][p], w2, s);
                    FMA2(acc[3][p], w3, s);
                }
            }
        }
    }

    const size_t rowbase = ((size_t)bt*HH + py)*WW;
    #pragma unroll
    for (int p = 0; p < 4; p++) {
        float* __restrict__ o = g_gx + (rowbase + px0 + p)*GG + co0;
        *(float2*)(o + 0*COUT) = acc[0][p];
        *(float2*)(o + 1*COUT) = acc[1][p];
        *(float2*)(o + 2*COUT) = acc[2][p];
        *(float2*)(o + 3*COUT) = acc[3][p];
    }
}

// ---------------------------------------------------------------------------
// Phase 2: one recurrent step.
// Thread: 4 pixels x (2 channels x 4 gates) = 32 accumulators.
// Block: 128 thr = 4 pixel-groups (16 px) x 32 channel-groups.
// Grid: B*H*4 = 1024.
// ---------------------------------------------------------------------------
template<bool FIRST>
__global__ __launch_bounds__(128, 5)
void step_kernel(const float* __restrict__ rw,
                 float* __restrict__ y,
                 const int t,
                 const float* __restrict__ gamma,
                 const float* __restrict__ beta,
                 const float* __restrict__ mmean,
                 const float* __restrict__ mvar)
{
    const float* __restrict__ hprev = (t & 1) ? g_h0 : g_h1;
    float*       __restrict__ hnew  = (t & 1) ? g_h1 : g_h0;

    const int tx  = threadIdx.x;
    const int co0 = (tx & 31) * 2;           // 0,2,...,62
    const int pg  = tx >> 5;                 // 0..3
    const int bid = blockIdx.x;
    const int b   = bid >> 8;
    const int r   = bid & 255;
    const int py  = r >> 2;
    const int px0 = (r & 3) * 16 + pg * 4;

    float2 acc[4][4];                        // [gate][pixel]
    const size_t gxrow = ((size_t)(b*TT + t)*HH + py)*WW;
    #pragma unroll
    for (int p = 0; p < 4; p++) {
        const float* __restrict__ gp = g_gx + (gxrow + px0 + p)*GG + co0;
        acc[0][p] = *(const float2*)(gp + 0*COUT);
        acc[1][p] = *(const float2*)(gp + 1*COUT);
        acc[2][p] = *(const float2*)(gp + 2*COUT);
        acc[3][p] = *(const float2*)(gp + 3*COUT);
    }

    if (!FIRST) {
        #pragma unroll
        for (int ky = 0; ky < 3; ky++) {
            const int iy = py + ky - 1;
            if ((unsigned)iy >= HH) continue;
            const float* __restrict__ hrow = hprev + ((size_t)(b*HH + iy)*WW)*COUT;
            #pragma unroll 1
            for (int ci = 0; ci < COUT; ci++) {
                float hv[6];
                #pragma unroll
                for (int j = 0; j < 6; j++) {
                    const int ix = px0 - 1 + j;
                    hv[j] = ((unsigned)ix < WW) ? hrow[(size_t)ix*COUT + ci] : 0.0f;
                }
                #pragma unroll
                for (int kx = 0; kx < 3; kx++) {
                    const float* __restrict__ wr = rw + (size_t)((ky*3+kx)*COUT + ci)*GG + co0;
                    float2 w0 = *(const float2*)(wr + 0*COUT);
                    float2 w1 = *(const float2*)(wr + 1*COUT);
                    float2 w2 = *(const float2*)(wr + 2*COUT);
                    float2 w3 = *(const float2*)(wr + 3*COUT);
                    #pragma unroll
                    for (int p = 0; p < 4; p++) {
                        const float s = hv[p + kx];
                        FMA2(acc[0][p], w0, s);
                        FMA2(acc[1][p], w1, s);
                        FMA2(acc[2][p], w2, s);
                        FMA2(acc[3][p], w3, s);
                    }
                }
            }
        }
    }

    // BN constants for this thread's 2 channels
    float2 gm  = *(const float2*)(gamma + co0);
    float2 bt2 = *(const float2*)(beta  + co0);
    float2 mm  = *(const float2*)(mmean + co0);
    float2 mv  = *(const float2*)(mvar  + co0);
    float2 inv, add;
    inv.x = gm.x * rsqrtf(mv.x + 1e-3f); add.x = bt2.x - mm.x*inv.x;
    inv.y = gm.y * rsqrtf(mv.y + 1e-3f); add.y = bt2.y - mm.y*inv.y;

    const size_t pixrow = ((size_t)b*HH + py)*WW;
    #pragma unroll
    for (int p = 0; p < 4; p++) {
        const size_t pix = pixrow + px0 + p;

        float2 i2, f2, o2;
        i2.x = hsig(acc[0][p].x); i2.y = hsig(acc[0][p].y);
        f2.x = hsig(acc[1][p].x); f2.y = hsig(acc[1][p].y);
        o2.x = hsig(acc[3][p].x); o2.y = hsig(acc[3][p].y);

        float* __restrict__ cp = g_c + pix*COUT + co0;
        float2 cold = FIRST ? make_float2(0.f,0.f) : *(const float2*)cp;

        float2 cn;
        cn.x = f2.x*cold.x + i2.x*tanhf(acc[2][p].x);
        cn.y = f2.y*cold.y + i2.y*tanhf(acc[2][p].y);
        *(float2*)cp = cn;

        float2 h2;
        h2.x = o2.x * tanhf(cn.x);
        h2.y = o2.y * tanhf(cn.y);
        *(float2*)(hnew + pix*COUT + co0) = h2;

        float2 yv;
        yv.x = h2.x*inv.x + add.x;
        yv.y = h2.y*inv.y + add.y;
        float* __restrict__ yp = y + (gxrow + px0 + p)*COUT + co0;
        *(float2*)yp = yv;
    }
}

extern "C" void kernel_launch(void* const* d_in, const int* in_sizes, int n_in,
                              void* d_out, int out_size)
{
    const float* x      = (const float*)d_in[0];
    const float* wk     = (const float*)d_in[1];
    const float* rw     = (const float*)d_in[2];
    const float* bias   = (const float*)d_in[3];
    const float* gamma  = (const float*)d_in[4];
    const float* beta   = (const float*)d_in[5];
    const float* mmean  = (const float*)d_in[6];
    const float* mvar   = (const float*)d_in[7];
    float* y = (float*)d_out;

    // Phase 1: all input convs. 16384 blocks x 128 threads (16 px each).
    input_conv_kernel<<<BB*TT*HH*4, 128>>>(x, wk, bias);

    // Phase 2: 16 sequential recurrent steps. 1024 blocks x 128 threads.
    const int nblk = BB*HH*4;
    step_kernel<true><<<nblk, 128>>>(rw, y, 0, gamma, beta, mmean, mvar);
    for (int t = 1; t < TT; t++) {
        step_kernel<false><<<nblk, 128>>>(rw, y, t, gamma, beta, mmean, mvar);
    }
}

// round 4
// speedup vs baseline: 4.1178x; 1.2163x over previous
#include <cuda_runtime.h>
#include <math.h>

#define BB 4
#define TT 16
#define HH 64
#define WW 64
#define CIN 32
#define COUT 64
#define GG (4*COUT)   // 256 gate channels

typedef unsigned long long u64;

// Scratch: gx for all (b,t) pixels: (B*T*H*W, 256) floats = 268MB
__device__ float g_gx[(size_t)BB*TT*HH*WW*GG];
// Ping-pong hidden state + cell state: (B*H*W, 64)
__device__ float g_h0[BB*HH*WW*COUT];
__device__ float g_h1[BB*HH*WW*COUT];
__device__ float g_c [BB*HH*WW*COUT];

__device__ __forceinline__ float hsig(float z) {
    return fminf(fmaxf(0.2f*z + 0.5f, 0.0f), 1.0f);
}

// Packed dual-FMA: acc.{lo,hi} += s.{lo,hi} * w.{lo,hi}  (one fma pipe slot)
__device__ __forceinline__ void fma_x2(u64& acc, u64 s, u64 w) {
    asm("fma.rn.f32x2 %0, %1, %2, %3;" : "=l"(acc) : "l"(s), "l"(w), "l"(acc));
}
// Broadcast a scalar into both halves of a 64-bit packed register.
__device__ __forceinline__ u64 pack2(float s) {
    u64 r;
    asm("mov.b64 %0, {%1, %1};" : "=l"(r) : "f"(s));
    return r;
}
__device__ __forceinline__ float2 unpack2(u64 v) {
    float2 f;
    asm("mov.b64 {%0, %1}, %2;" : "=f"(f.x), "=f"(f.y) : "l"(v));
    return f;
}

// ---------------------------------------------------------------------------
// Phase 1: input-to-gate conv.
// Thread: 4 pixels x (2 channels x 4 gates) = 16 packed accumulators.
// Block: 128 thr = 4 pixel-groups (16 px) x 32 channel-groups.
// Grid: B*T*H*4 = 16384.
// ---------------------------------------------------------------------------
__global__ __launch_bounds__(128, 5)
void input_conv_kernel(const float* __restrict__ x,
                       const float* __restrict__ wk,
                       const float* __restrict__ bias)
{
    const int tx  = threadIdx.x;
    const int co0 = (tx & 31) * 2;           // 0,2,...,62
    const int pg  = tx >> 5;                 // 0..3  (== warp id)
    const int bid = blockIdx.x;
    const int bt  = bid >> 8;                // /256
    const int r   = bid & 255;
    const int py  = r >> 2;
    const int px0 = (r & 3) * 16 + pg * 4;

    u64 acc[4][4];                           // [gate][pixel]
    #pragma unroll
    for (int g = 0; g < 4; g++) {
        u64 bv = *(const u64*)(bias + g*COUT + co0);
        #pragma unroll
        for (int p = 0; p < 4; p++) acc[g][p] = bv;
    }

    #pragma unroll
    for (int ky = 0; ky < 3; ky++) {
        const int iy = py + ky - 1;
        if ((unsigned)iy >= HH) continue;
        const float* __restrict__ xrow = x + ((size_t)(bt*HH + iy)*WW)*CIN;
        #pragma unroll 1
        for (int ci = 0; ci < CIN; ci++) {
            u64 hv2[6];
            #pragma unroll
            for (int j = 0; j < 6; j++) {
                const int ix = px0 - 1 + j;
                hv2[j] = pack2(((unsigned)ix < WW) ? xrow[(size_t)ix*CIN + ci] : 0.0f);
            }
            #pragma unroll
            for (int kx = 0; kx < 3; kx++) {
                const float* __restrict__ wr = wk + (size_t)((ky*3+kx)*CIN + ci)*GG + co0;
                u64 w0 = *(const u64*)(wr + 0*COUT);
                u64 w1 = *(const u64*)(wr + 1*COUT);
                u64 w2 = *(const u64*)(wr + 2*COUT);
                u64 w3 = *(const u64*)(wr + 3*COUT);
                #pragma unroll
                for (int p = 0; p < 4; p++) {
                    const u64 s2 = hv2[p + kx];
                    fma_x2(acc[0][p], s2, w0);
                    fma_x2(acc[1][p], s2, w1);
                    fma_x2(acc[2][p], s2, w2);
                    fma_x2(acc[3][p], s2, w3);
                }
            }
        }
    }

    const size_t rowbase = ((size_t)bt*HH + py)*WW;
    #pragma unroll
    for (int p = 0; p < 4; p++) {
        float* __restrict__ o = g_gx + (rowbase + px0 + p)*GG + co0;
        *(u64*)(o + 0*COUT) = acc[0][p];
        *(u64*)(o + 1*COUT) = acc[1][p];
        *(u64*)(o + 2*COUT) = acc[2][p];
        *(u64*)(o + 3*COUT) = acc[3][p];
    }
}

// ---------------------------------------------------------------------------
// Phase 2: one recurrent step.
// Thread: 4 pixels x (2 channels x 4 gates) = 16 packed accumulators.
// Block: 128 thr = 4 pixel-groups (16 px) x 32 channel-groups.
// Grid: B*H*4 = 1024.
// ---------------------------------------------------------------------------
template<bool FIRST>
__global__ __launch_bounds__(128, 5)
void step_kernel(const float* __restrict__ rw,
                 float* __restrict__ y,
                 const int t,
                 const float* __restrict__ gamma,
                 const float* __restrict__ beta,
                 const float* __restrict__ mmean,
                 const float* __restrict__ mvar)
{
    const float* __restrict__ hprev = (t & 1) ? g_h0 : g_h1;
    float*       __restrict__ hnew  = (t & 1) ? g_h1 : g_h0;

    const int tx  = threadIdx.x;
    const int co0 = (tx & 31) * 2;           // 0,2,...,62
    const int pg  = tx >> 5;                 // 0..3
    const int bid = blockIdx.x;
    const int b   = bid >> 8;
    const int r   = bid & 255;
    const int py  = r >> 2;
    const int px0 = (r & 3) * 16 + pg * 4;

    u64 acc[4][4];                           // [gate][pixel]
    const size_t gxrow = ((size_t)(b*TT + t)*HH + py)*WW;
    #pragma unroll
    for (int p = 0; p < 4; p++) {
        const float* __restrict__ gp = g_gx + (gxrow + px0 + p)*GG + co0;
        acc[0][p] = *(const u64*)(gp + 0*COUT);
        acc[1][p] = *(const u64*)(gp + 1*COUT);
        acc[2][p] = *(const u64*)(gp + 2*COUT);
        acc[3][p] = *(const u64*)(gp + 3*COUT);
    }

    if (!FIRST) {
        #pragma unroll
        for (int ky = 0; ky < 3; ky++) {
            const int iy = py + ky - 1;
            if ((unsigned)iy >= HH) continue;
            const float* __restrict__ hrow = hprev + ((size_t)(b*HH + iy)*WW)*COUT;
            #pragma unroll 1
            for (int ci = 0; ci < COUT; ci++) {
                u64 hv2[6];
                #pragma unroll
                for (int j = 0; j < 6; j++) {
                    const int ix = px0 - 1 + j;
                    hv2[j] = pack2(((unsigned)ix < WW) ? hrow[(size_t)ix*COUT + ci] : 0.0f);
                }
                #pragma unroll
                for (int kx = 0; kx < 3; kx++) {
                    const float* __restrict__ wr = rw + (size_t)((ky*3+kx)*COUT + ci)*GG + co0;
                    u64 w0 = *(const u64*)(wr + 0*COUT);
                    u64 w1 = *(const u64*)(wr + 1*COUT);
                    u64 w2 = *(const u64*)(wr + 2*COUT);
                    u64 w3 = *(const u64*)(wr + 3*COUT);
                    #pragma unroll
                    for (int p = 0; p < 4; p++) {
                        const u64 s2 = hv2[p + kx];
                        fma_x2(acc[0][p], s2, w0);
                        fma_x2(acc[1][p], s2, w1);
                        fma_x2(acc[2][p], s2, w2);
                        fma_x2(acc[3][p], s2, w3);
                    }
                }
            }
        }
    }

    // BN constants for this thread's 2 channels
    float2 gm  = *(const float2*)(gamma + co0);
    float2 bt2 = *(const float2*)(beta  + co0);
    float2 mm  = *(const float2*)(mmean + co0);
    float2 mv  = *(const float2*)(mvar  + co0);
    float2 inv, add;
    inv.x = gm.x * rsqrtf(mv.x + 1e-3f); add.x = bt2.x - mm.x*inv.x;
    inv.y = gm.y * rsqrtf(mv.y + 1e-3f); add.y = bt2.y - mm.y*inv.y;

    const size_t pixrow = ((size_t)b*HH + py)*WW;
    #pragma unroll
    for (int p = 0; p < 4; p++) {
        const size_t pix = pixrow + px0 + p;

        float2 gi = unpack2(acc[0][p]);
        float2 gf = unpack2(acc[1][p]);
        float2 gg = unpack2(acc[2][p]);
        float2 go = unpack2(acc[3][p]);

        float2 i2, f2, o2;
        i2.x = hsig(gi.x); i2.y = hsig(gi.y);
        f2.x = hsig(gf.x); f2.y = hsig(gf.y);
        o2.x = hsig(go.x); o2.y = hsig(go.y);

        float* __restrict__ cp = g_c + pix*COUT + co0;
        float2 cold = FIRST ? make_float2(0.f,0.f) : *(const float2*)cp;

        float2 cn;
        cn.x = f2.x*cold.x + i2.x*tanhf(gg.x);
        cn.y = f2.y*cold.y + i2.y*tanhf(gg.y);
        *(float2*)cp = cn;

        float2 h2;
        h2.x = o2.x * tanhf(cn.x);
        h2.y = o2.y * tanhf(cn.y);
        *(float2*)(hnew + pix*COUT + co0) = h2;

        float2 yv;
        yv.x = h2.x*inv.x + add.x;
        yv.y = h2.y*inv.y + add.y;
        float* __restrict__ yp = y + (gxrow + px0 + p)*COUT + co0;
        *(float2*)yp = yv;
    }
}

extern "C" void kernel_launch(void* const* d_in, const int* in_sizes, int n_in,
                              void* d_out, int out_size)
{
    const float* x      = (const float*)d_in[0];
    const float* wk     = (const float*)d_in[1];
    const float* rw     = (const float*)d_in[2];
    const float* bias   = (const float*)d_in[3];
    const float* gamma  = (const float*)d_in[4];
    const float* beta   = (const float*)d_in[5];
    const float* mmean  = (const float*)d_in[6];
    const float* mvar   = (const float*)d_in[7];
    float* y = (float*)d_out;

    // Phase 1: all input convs. 16384 blocks x 128 threads (16 px each).
    input_conv_kernel<<<BB*TT*HH*4, 128>>>(x, wk, bias);

    // Phase 2: 16 sequential recurrent steps. 1024 blocks x 128 threads.
    const int nblk = BB*HH*4;
    step_kernel<true><<<nblk, 128>>>(rw, y, 0, gamma, beta, mmean, mvar);
    for (int t = 1; t < TT; t++) {
        step_kernel<false><<<nblk, 128>>>(rw, y, t, gamma, beta, mmean, mvar);
    }
}